// round 5
// baseline (speedup 1.0000x reference)
#include <cuda_runtime.h>
#include <cstdint>
#include <cstddef>

#define T_STEPS 256
#define BATCH   32
#define EMB     256
#define LAT     512
#define OUT_DIM 32000
#define MROWS   (T_STEPS * BATCH)   // 8192

// ---------------- device scratch (no allocations allowed) ------------------
__device__ float g_xproj[(size_t)MROWS * LAT];      // 16 MB
__device__ float g_hA[(size_t)MROWS * LAT];         // 16 MB, A fragment-major (tf32)
__device__ float g_WoB[(size_t)OUT_DIM * LAT];      // 65.5 MB, B fragment-major (tf32)

// ---------------- helpers ----------------------------------------------------
__device__ __forceinline__ unsigned long long pack2(float a, float b) {
    unsigned long long r;
    asm("mov.b64 %0, {%1, %2};" : "=l"(r) : "f"(a), "f"(b));
    return r;
}
__device__ __forceinline__ void ffma2(unsigned long long& acc, unsigned long long h,
                                      unsigned long long w) {
    asm("fma.rn.f32x2 %0, %1, %2, %0;" : "+l"(acc) : "l"(h), "l"(w));
}
__device__ __forceinline__ void unpack2(unsigned long long v, float& a, float& b) {
    asm("mov.b64 {%0, %1}, %2;" : "=f"(a), "=f"(b) : "l"(v));
}
__device__ __forceinline__ float to_tf32(float f) {
    uint32_t o;
    asm("cvt.rna.tf32.f32 %0, %1;" : "=r"(o) : "f"(f));
    return __uint_as_float(o);
}
__device__ __forceinline__ uint32_t smaddr(const void* p) {
    return (uint32_t)__cvta_generic_to_shared(p);
}
__device__ __forceinline__ uint32_t elect_one_pred() {
    uint32_t pred;
    asm volatile(
        "{\n\t.reg .pred p;\n\t"
        "elect.sync _|p, 0xFFFFFFFF;\n\t"
        "selp.b32 %0, 1, 0, p;\n\t}"
        : "=r"(pred));
    return pred;
}
__device__ __forceinline__ void lds128(uint32_t a, uint32_t& r0, uint32_t& r1,
                                       uint32_t& r2, uint32_t& r3) {
    asm volatile("ld.shared.v4.b32 {%0, %1, %2, %3}, [%4];"
                 : "=r"(r0), "=r"(r1), "=r"(r2), "=r"(r3) : "r"(a));
}
__device__ __forceinline__ void bulk_g2s(uint32_t dst, const void* src,
                                         uint32_t bytes, uint32_t mbar) {
    asm volatile(
        "cp.async.bulk.shared::cluster.global.mbarrier::complete_tx::bytes "
        "[%0], [%1], %2, [%3];"
        :: "r"(dst), "l"(src), "r"(bytes), "r"(mbar) : "memory");
}
#define MBARRIER_INIT(mbar, cnt) \
    asm volatile("mbarrier.init.shared.b64 [%0], %1;" \
                 :: "r"((uint32_t)(mbar)), "r"((uint32_t)(cnt)) : "memory")
#define MBARRIER_ARRIVE(mbar) \
    asm volatile("mbarrier.arrive.shared.b64 _, [%0];" \
                 :: "r"((uint32_t)(mbar)) : "memory")
#define MBARRIER_EXPECT_TX(mbar, tx) \
    asm volatile("mbarrier.arrive.expect_tx.shared.b64 _, [%0], %1;" \
                 :: "r"((uint32_t)(mbar)), "r"((uint32_t)(tx)) : "memory")
#define MBARRIER_WAIT_PARITY(mbar, par) do {                                   \
    uint32_t _m = (uint32_t)(mbar);                                            \
    uint32_t _p = (uint32_t)(par);                                             \
    asm volatile(                                                              \
        "{\n\t.reg .pred P1;\n\t"                                              \
        "WL_%=:\n\t"                                                           \
        "mbarrier.try_wait.parity.acquire.cta.shared::cta.b64 P1, [%0], %1, 0x989680;\n\t" \
        "@P1 bra.uni WD_%=;\n\t"                                               \
        "bra.uni WL_%=;\n\t"                                                   \
        "WD_%=:\n\t}"                                                          \
        :: "r"(_m), "r"(_p) : "memory");                                       \
} while (0)
#define FENCE_ASYNC_SHARED() asm volatile("fence.proxy.async.shared::cta;" ::: "memory")
#define CLUSTER_SYNC() do { \
    asm volatile("barrier.cluster.arrive.aligned;" ::: "memory"); \
    asm volatile("barrier.cluster.wait.aligned;" ::: "memory"); \
} while (0)

__device__ __forceinline__ void mma_tf32(float& c0, float& c1, float& c2, float& c3,
                                         uint32_t a0, uint32_t a1, uint32_t a2, uint32_t a3,
                                         uint32_t b0, uint32_t b1) {
    asm volatile(
        "mma.sync.aligned.m16n8k8.row.col.f32.tf32.tf32.f32 "
        "{%0,%1,%2,%3}, {%4,%5,%6,%7}, {%8,%9}, {%0,%1,%2,%3};"
        : "+f"(c0), "+f"(c1), "+f"(c2), "+f"(c3)
        : "r"(a0), "r"(a1), "r"(a2), "r"(a3), "r"(b0), "r"(b1));
}

// Fragment-major index for A value at (row m, col k), tf32, m16n8k8 layout.
__device__ __forceinline__ size_t hA_index(int m, int k) {
    int mt = m >> 7, mi16 = (m >> 4) & 7, r = m & 15;
    int kt = k >> 5, kk = (k >> 3) & 3, kb = k & 7;
    int lane = (r & 7) * 4 + (kb & 3);
    int j = (r >> 3) + 2 * (kb >> 2);
    return ((size_t)mt * 16 + kt) * 4096 + (size_t)((mi16 * 4 + kk) * 128 + lane * 4 + j);
}

// ============================================================================
// Kernel 1: xproj = gather(emb, x) @ W_h[:256] + b_h  (fp32 SIMT)
// ============================================================================
__global__ void __launch_bounds__(256) k_xproj(const int* __restrict__ x,
                                               const float* __restrict__ emb,
                                               const float* __restrict__ Wh,
                                               const float* __restrict__ bh)
{
    __shared__ float As[64][36];
    __shared__ float Bs[32][132];
    __shared__ int   xs[64];

    const int tid = threadIdx.x;
    const int m0  = blockIdx.y * 64;
    const int n0  = blockIdx.x * 128;

    if (tid < 64) xs[tid] = x[m0 + tid];
    __syncthreads();

    const int ty = tid >> 5;
    const int tx = tid & 31;

    float acc[8][4];
#pragma unroll
    for (int i = 0; i < 8; i++)
#pragma unroll
        for (int j = 0; j < 4; j++) acc[i][j] = 0.f;

    for (int k0 = 0; k0 < EMB; k0 += 32) {
#pragma unroll
        for (int q = 0; q < 2; q++) {
            int f = tid + q * 256;
            int r = f >> 3, c4 = f & 7;
            float4 v = *(const float4*)(emb + (size_t)xs[r] * EMB + k0 + c4 * 4);
            *(float4*)(&As[r][c4 * 4]) = v;
        }
#pragma unroll
        for (int q = 0; q < 4; q++) {
            int f = tid + q * 256;
            int r = f >> 5, c4 = f & 31;
            float4 v = *(const float4*)(Wh + (size_t)(k0 + r) * LAT + n0 + c4 * 4);
            *(float4*)(&Bs[r][c4 * 4]) = v;
        }
        __syncthreads();

#pragma unroll
        for (int kq = 0; kq < 8; kq++) {
            float bt[4][4];
#pragma unroll
            for (int kk = 0; kk < 4; kk++) {
                float4 t = *(float4*)(&Bs[kq * 4 + kk][tx * 4]);
                bt[kk][0] = t.x; bt[kk][1] = t.y; bt[kk][2] = t.z; bt[kk][3] = t.w;
            }
#pragma unroll
            for (int i = 0; i < 8; i++) {
                float4 a4 = *(float4*)(&As[ty * 8 + i][kq * 4]);
#pragma unroll
                for (int j = 0; j < 4; j++) {
                    acc[i][j] = fmaf(a4.x, bt[0][j],
                                fmaf(a4.y, bt[1][j],
                                fmaf(a4.z, bt[2][j],
                                fmaf(a4.w, bt[3][j], acc[i][j]))));
                }
            }
        }
        __syncthreads();
    }

    float4 bh4 = *(const float4*)(bh + n0 + tx * 4);
#pragma unroll
    for (int i = 0; i < 8; i++) {
        float4 o;
        o.x = acc[i][0] + bh4.x;
        o.y = acc[i][1] + bh4.y;
        o.z = acc[i][2] + bh4.z;
        o.w = acc[i][3] + bh4.w;
        *(float4*)(g_xproj + (size_t)(m0 + ty * 8 + i) * LAT + n0 + tx * 4) = o;
    }
}

// ============================================================================
// Kernel 1b: build g_WoB — B fragment-major, tf32-converted.
// ============================================================================
__global__ void __launch_bounds__(256) k_prepB(const float* __restrict__ Wo)
{
    const int nt = blockIdx.x, kt = blockIdx.y;
    const int w = threadIdx.x >> 5, lane = threadIdx.x & 31;
    const size_t panel = ((size_t)nt * 16 + kt) * 8192;

#pragma unroll
    for (int bi = 0; bi < 8; bi++) {
        int b  = w * 8 + bi;
        int wn = b >> 4, kk = (b >> 2) & 3, np = b & 3;
        int k0 = kt * 32 + kk * 8 + (lane & 3);
        int n0 = nt * 256 + wn * 64 + np * 16 + (lane >> 2);
        const float* base = Wo + (size_t)k0 * OUT_DIM + n0;
        float4 v;
        v.x = to_tf32(base[0]);
        v.y = to_tf32(base[(size_t)4 * OUT_DIM]);
        v.z = to_tf32(base[8]);
        v.w = to_tf32(base[(size_t)4 * OUT_DIM + 8]);
        *(float4*)(g_WoB + panel + (size_t)b * 128 + lane * 4) = v;
    }
}

// ============================================================================
// Kernel 2: clustered recurrence. 16 clusters of 8 CTAs (one per batch pair).
// CTA = 64 cols, 256 threads = 8 k-slices x 32 cols (2 cols/thread).
// h kept in smem double-buffered, pre-duplicated {(b0,b0),(b1,b1)} per k.
// Exchange: 64 writer threads store 16B to all 8 cluster CTAs via DSMEM,
// then barrier.cluster (release/acquire orders the shared::cluster stores).
// ============================================================================
__global__ void __launch_bounds__(256, 1) __cluster_dims__(8, 1, 1)
k_rnn_cl(const float* __restrict__ Wh, float* __restrict__ hid)
{
    __shared__ ulonglong2 hbuf[2][512];   // 16 KB: [buf][k] = {(b0,b0),(b1,b1)}
    __shared__ float      red[8][2][64];  // 4 KB:  [slice][batch][localcol]

    const int tid = threadIdx.x;
    const int s   = tid >> 5;             // 0..7  k-slice of 64
    const int c   = tid & 31;             // 0..31
    uint32_t rank;
    asm("mov.u32 %0, %%cluster_ctarank;" : "=r"(rank));
    const int bgrp = blockIdx.x >> 3;     // 0..15 (2 batches each)
    const int col0 = (int)rank * 64 + c;  // this thread's first col
    const int b0   = bgrp * 2;

    // W_hh slice: packed (w[col0], w[col0+32]) per k. 64 x u64 regs.
    unsigned long long w2[64];
#pragma unroll
    for (int i = 0; i < 64; i++) {
        const float* wr = Wh + (size_t)(EMB + s * 64 + i) * LAT + col0;
        w2[i] = pack2(wr[0], wr[32]);
    }

    // zero read buffer 0 (h_{-1} = 0)
    hbuf[0][tid]       = make_ulonglong2(0ull, 0ull);
    hbuf[0][tid + 256] = make_ulonglong2(0ull, 0ull);
    __syncthreads();
    CLUSTER_SYNC();   // peers initialized before any remote writes

    const uint32_t hb_base = smaddr(&hbuf[0][0]);

#pragma unroll 1
    for (int t = 0; t < T_STEPS; t++) {
        const int rb = t & 1;
        // prefetch xproj for this step (consumed after compute)
        float xp0 = 0.f, xp1 = 0.f;
        if (tid < 64) {
            const float* xp = g_xproj + (size_t)(t * BATCH + b0) * LAT
                              + (int)rank * 64 + tid;
            xp0 = __ldg(xp);
            xp1 = __ldg(xp + LAT);
        }

        // partial matvec over this slice's 64 k values
        unsigned long long accb0 = 0ull, accb1 = 0ull;
        const ulonglong2* hr = &hbuf[rb][s * 64];
#pragma unroll
        for (int i = 0; i < 64; i++) {
            ulonglong2 hv = hr[i];
            ffma2(accb0, hv.x, w2[i]);   // batch0: (col0, col0+32)
            ffma2(accb1, hv.y, w2[i]);   // batch1
        }
        float p00, p01, p10, p11;
        unpack2(accb0, p00, p01);
        unpack2(accb1, p10, p11);
        red[s][0][c]      = p00;
        red[s][0][c + 32] = p01;
        red[s][1][c]      = p10;
        red[s][1][c + 32] = p11;
        __syncthreads();

        // reduce + relu + publish
        if (tid < 64) {
            float v0 = xp0, v1 = xp1;
#pragma unroll
            for (int ss = 0; ss < 8; ss++) {
                v0 += red[ss][0][tid];
                v1 += red[ss][1][tid];
            }
            v0 = fmaxf(v0, 0.f);
            v1 = fmaxf(v1, 0.f);

            const int col = (int)rank * 64 + tid;
            const int row0 = t * BATCH + b0;
            hid[(size_t)row0 * LAT + col]       = v0;
            hid[(size_t)(row0 + 1) * LAT + col] = v1;
            g_hA[hA_index(row0, col)]     = to_tf32(v0);
            g_hA[hA_index(row0 + 1, col)] = to_tf32(v1);

            unsigned long long d0 = pack2(v0, v0);
            unsigned long long d1 = pack2(v1, v1);
            const uint32_t lofs = hb_base + (uint32_t)(((rb ^ 1) * 512 + col) * 16);
#pragma unroll
            for (int r = 0; r < 8; r++) {
                uint32_t ra;
                asm("mapa.shared::cluster.u32 %0, %1, %2;"
                    : "=r"(ra) : "r"(lofs), "r"((uint32_t)r));
                asm volatile("st.shared::cluster.b64 [%0], %1;"
                             :: "r"(ra), "l"(d0) : "memory");
                asm volatile("st.shared::cluster.b64 [%0+8], %1;"
                             :: "r"(ra), "l"(d1) : "memory");
            }
        }
        CLUSTER_SYNC();   // release stores / acquire for next step's reads
    }
}

// ============================================================================
// Kernel 3: out = hid @ Wo + bo.  mma.sync tf32, fragment-major operands,
// cp.async.bulk 4-stage mbarrier ring. (unchanged from round 4)
// ============================================================================
#define NSTG 4
#define A_PANEL_B 16384u
#define B_PANEL_B 32768u
#define STG_B (A_PANEL_B + B_PANEL_B)            // 49152
#define TILE_OFF 1024u
#define OUT_SMEM (TILE_OFF + NSTG * STG_B)       // 197632 B

__global__ void __launch_bounds__(256, 1) k_out_mma(const float* __restrict__ bo,
                                                    float* __restrict__ out)
{
    extern __shared__ char smem[];
    const uint32_t smem_base = smaddr(smem);
    const uint32_t fullb  = smem_base;
    const uint32_t emptyb = smem_base + 32;

    const int tid  = threadIdx.x;
    const int warp = tid >> 5;
    const int lane = tid & 31;
    const int wm   = warp >> 2;
    const int wn   = warp & 3;
    const int mt   = blockIdx.x;
    const int nt   = blockIdx.y;

    if (tid == 0) {
#pragma unroll
        for (int s2 = 0; s2 < NSTG; s2++) {
            MBARRIER_INIT(fullb  + s2 * 8, 1);
            MBARRIER_INIT(emptyb + s2 * 8, 8);
        }
        FENCE_ASYNC_SHARED();
    }
    __syncthreads();

    const float* gA = g_hA  + (size_t)mt * 16 * 4096;
    const float* gB = g_WoB + (size_t)nt * 16 * 8192;

    auto issue = [&](int cc) {
        int st = cc & 3;
        uint32_t sa = smem_base + TILE_OFF + st * STG_B;
        MBARRIER_EXPECT_TX(fullb + st * 8, STG_B);
        bulk_g2s(sa,             gA + (size_t)cc * 4096, A_PANEL_B, fullb + st * 8);
        bulk_g2s(sa + A_PANEL_B, gB + (size_t)cc * 8192, B_PANEL_B, fullb + st * 8);
    };

    if (tid == 0) {
        issue(0); issue(1); issue(2); issue(3);
    }

    float acc[4][8][4];
#pragma unroll
    for (int mi = 0; mi < 4; mi++)
#pragma unroll
        for (int ni = 0; ni < 8; ni++)
#pragma unroll
            for (int j = 0; j < 4; j++) acc[mi][ni][j] = 0.f;

#pragma unroll 1
    for (int c = 0; c < 16; c++) {
        const int st = c & 3;
        const int ph = (c >> 2) & 1;
        MBARRIER_WAIT_PARITY(fullb + st * 8, ph);

        const uint32_t sa = smem_base + TILE_OFF + st * STG_B;
        const uint32_t sb = sa + A_PANEL_B;

#pragma unroll
        for (int kk = 0; kk < 4; kk++) {
            uint32_t af[4][4];
#pragma unroll
            for (int mi = 0; mi < 4; mi++)
                lds128(sa + (uint32_t)(((wm * 4 + mi) * 4 + kk) * 512 + lane * 16),
                       af[mi][0], af[mi][1], af[mi][2], af[mi][3]);
            uint32_t bf[4][4];
#pragma unroll
            for (int np = 0; np < 4; np++)
                lds128(sb + (uint32_t)((((wn * 4 + kk) * 4) + np) * 512 + lane * 16),
                       bf[np][0], bf[np][1], bf[np][2], bf[np][3]);
#pragma unroll
            for (int mi = 0; mi < 4; mi++) {
#pragma unroll
                for (int np = 0; np < 4; np++) {
                    mma_tf32(acc[mi][2 * np][0], acc[mi][2 * np][1],
                             acc[mi][2 * np][2], acc[mi][2 * np][3],
                             af[mi][0], af[mi][1], af[mi][2], af[mi][3],
                             bf[np][0], bf[np][1]);
                    mma_tf32(acc[mi][2 * np + 1][0], acc[mi][2 * np + 1][1],
                             acc[mi][2 * np + 1][2], acc[mi][2 * np + 1][3],
                             af[mi][0], af[mi][1], af[mi][2], af[mi][3],
                             bf[np][2], bf[np][3]);
                }
            }
        }

        if (elect_one_pred()) MBARRIER_ARRIVE(emptyb + st * 8);
        if (tid == 0 && c < 12) {
            MBARRIER_WAIT_PARITY(emptyb + st * 8, ph);
            issue(c + 4);
        }
    }

    const int m0 = mt * 128 + wm * 64;
    const int n0 = nt * 256 + wn * 64;
#pragma unroll
    for (int ni = 0; ni < 8; ni++) {
        int ccol = n0 + ni * 8 + (lane & 3) * 2;
        float2 b2 = *(const float2*)(bo + ccol);
#pragma unroll
        for (int mi = 0; mi < 4; mi++) {
            int r = m0 + mi * 16 + (lane >> 2);
            float2 o0, o1;
            o0.x = acc[mi][ni][0] + b2.x;
            o0.y = acc[mi][ni][1] + b2.y;
            o1.x = acc[mi][ni][2] + b2.x;
            o1.y = acc[mi][ni][3] + b2.y;
            *(float2*)(out + (size_t)r * OUT_DIM + ccol)       = o0;
            *(float2*)(out + (size_t)(r + 8) * OUT_DIM + ccol) = o1;
        }
    }
}

// ============================================================================
extern "C" void kernel_launch(void* const* d_in, const int* in_sizes, int n_in,
                              void* d_out, int out_size)
{
    (void)in_sizes; (void)n_in; (void)out_size;
    const int*   x   = (const int*)d_in[0];
    const float* emb = (const float*)d_in[1];
    const float* Wh  = (const float*)d_in[2];
    const float* bh  = (const float*)d_in[3];
    const float* Wo  = (const float*)d_in[4];
    const float* bo  = (const float*)d_in[5];

    float* out = (float*)d_out;                       // [8192, 32000]
    float* hid = out + (size_t)MROWS * OUT_DIM;       // [8192, 512]

    cudaFuncSetAttribute(k_out_mma, cudaFuncAttributeMaxDynamicSharedMemorySize,
                         OUT_SMEM);

    k_xproj<<<dim3(4, 128), 256>>>(x, emb, Wh, bh);
    k_prepB<<<dim3(OUT_DIM / 256, LAT / 32), 256>>>(Wo);
    k_rnn_cl<<<128, 256>>>(Wh, hid);
    k_out_mma<<<dim3(MROWS / 128, OUT_DIM / 256), 256, OUT_SMEM>>>(bo, out);
}

// round 6
// speedup vs baseline: 1.4675x; 1.4675x over previous
#include <cuda_runtime.h>
#include <cuda_fp16.h>
#include <cstdint>
#include <cstddef>

#define T_STEPS 256
#define BATCH   32
#define EMB     256
#define LAT     512
#define OUT_DIM 32000
#define MROWS   (T_STEPS * BATCH)   // 8192

// ---------------- device scratch (no allocations allowed) ------------------
__device__ float    g_xproj[(size_t)MROWS * LAT];      // 16 MB
__device__ __half   g_hA[(size_t)MROWS * LAT];         // 8 MB, A fragment-major fp16
__device__ __half   g_WoB[(size_t)OUT_DIM * LAT];      // 32.75 MB, B fragment-major fp16
__device__ unsigned g_cnt[8];                           // rnn barrier counters

// ---------------- helpers ----------------------------------------------------
__device__ __forceinline__ unsigned long long pack2(float a, float b) {
    unsigned long long r;
    asm("mov.b64 %0, {%1, %2};" : "=l"(r) : "f"(a), "f"(b));
    return r;
}
__device__ __forceinline__ void unpack2(unsigned long long v, float& a, float& b) {
    asm("mov.b64 {%0, %1}, %2;" : "=f"(a), "=f"(b) : "l"(v));
}
__device__ __forceinline__ void ffma2(unsigned long long& acc, unsigned long long h,
                                      unsigned long long w) {
    asm("fma.rn.f32x2 %0, %1, %2, %0;" : "+l"(acc) : "l"(h), "l"(w));
}
__device__ __forceinline__ uint32_t pack_h2(float lo, float hi) {
    __half2 h = __floats2half2_rn(lo, hi);
    return *(uint32_t*)&h;
}
__device__ __forceinline__ uint32_t smaddr(const void* p) {
    return (uint32_t)__cvta_generic_to_shared(p);
}
__device__ __forceinline__ uint32_t elect_one_pred() {
    uint32_t pred;
    asm volatile(
        "{\n\t.reg .pred p;\n\t"
        "elect.sync _|p, 0xFFFFFFFF;\n\t"
        "selp.b32 %0, 1, 0, p;\n\t}"
        : "=r"(pred));
    return pred;
}
__device__ __forceinline__ void lds128(uint32_t a, uint32_t& r0, uint32_t& r1,
                                       uint32_t& r2, uint32_t& r3) {
    asm volatile("ld.shared.v4.b32 {%0, %1, %2, %3}, [%4];"
                 : "=r"(r0), "=r"(r1), "=r"(r2), "=r"(r3) : "r"(a));
}
__device__ __forceinline__ void bulk_g2s(uint32_t dst, const void* src,
                                         uint32_t bytes, uint32_t mbar) {
    asm volatile(
        "cp.async.bulk.shared::cluster.global.mbarrier::complete_tx::bytes "
        "[%0], [%1], %2, [%3];"
        :: "r"(dst), "l"(src), "r"(bytes), "r"(mbar) : "memory");
}
#define MBARRIER_INIT(mbar, cnt) \
    asm volatile("mbarrier.init.shared.b64 [%0], %1;" \
                 :: "r"((uint32_t)(mbar)), "r"((uint32_t)(cnt)) : "memory")
#define MBARRIER_ARRIVE(mbar) \
    asm volatile("mbarrier.arrive.shared.b64 _, [%0];" \
                 :: "r"((uint32_t)(mbar)) : "memory")
#define MBARRIER_EXPECT_TX(mbar, tx) \
    asm volatile("mbarrier.arrive.expect_tx.shared.b64 _, [%0], %1;" \
                 :: "r"((uint32_t)(mbar)), "r"((uint32_t)(tx)) : "memory")
#define MBARRIER_WAIT_PARITY(mbar, par) do {                                   \
    uint32_t _m = (uint32_t)(mbar);                                            \
    uint32_t _p = (uint32_t)(par);                                             \
    asm volatile(                                                              \
        "{\n\t.reg .pred P1;\n\t"                                              \
        "WL_%=:\n\t"                                                           \
        "mbarrier.try_wait.parity.acquire.cta.shared::cta.b64 P1, [%0], %1, 0x989680;\n\t" \
        "@P1 bra.uni WD_%=;\n\t"                                               \
        "bra.uni WL_%=;\n\t"                                                   \
        "WD_%=:\n\t}"                                                          \
        :: "r"(_m), "r"(_p) : "memory");                                       \
} while (0)
#define FENCE_ASYNC_SHARED() asm volatile("fence.proxy.async.shared::cta;" ::: "memory")

__device__ __forceinline__ void mma_f16(float& c0, float& c1, float& c2, float& c3,
                                        uint32_t a0, uint32_t a1, uint32_t a2, uint32_t a3,
                                        uint32_t b0, uint32_t b1) {
    asm volatile(
        "mma.sync.aligned.m16n8k16.row.col.f32.f16.f16.f32 "
        "{%0,%1,%2,%3}, {%4,%5,%6,%7}, {%8,%9}, {%0,%1,%2,%3};"
        : "+f"(c0), "+f"(c1), "+f"(c2), "+f"(c3)
        : "r"(a0), "r"(a1), "r"(a2), "r"(a3), "r"(b0), "r"(b1));
}

// Fragment-major index (in halfs) for A value at (row m, col k), fp16 m16n8k16.
// Panel (mt, kt32) = 4096 halfs: [mi16(8)][kk(2)][lane(32)][reg(4) x half(2)]
__device__ __forceinline__ size_t hA_index_h(int m, int k) {
    int mt = m >> 7, mi16 = (m >> 4) & 7, r = m & 15;
    int kt = k >> 5, kk = (k >> 4) & 1, kb = k & 15;
    int lane = (r & 7) * 4 + ((kb >> 1) & 3);
    int j = (r >> 3) + 2 * (kb >> 3);
    int h = kb & 1;
    return ((size_t)mt * 16 + kt) * 4096
         + (size_t)((((mi16 * 2 + kk) * 32 + lane) * 4 + j) * 2 + h);
}

// ============================================================================
// Kernel 1: xproj = gather(emb, x) @ W_h[:256] + b_h  (fp32 SIMT)
// ============================================================================
__global__ void __launch_bounds__(256) k_xproj(const int* __restrict__ x,
                                               const float* __restrict__ emb,
                                               const float* __restrict__ Wh,
                                               const float* __restrict__ bh)
{
    __shared__ float As[64][36];
    __shared__ float Bs[32][132];
    __shared__ int   xs[64];

    const int tid = threadIdx.x;
    const int m0  = blockIdx.y * 64;
    const int n0  = blockIdx.x * 128;

    if (blockIdx.x == 0 && blockIdx.y == 0 && tid < 8) g_cnt[tid] = 0;

    if (tid < 64) xs[tid] = x[m0 + tid];
    __syncthreads();

    const int ty = tid >> 5;
    const int tx = tid & 31;

    float acc[8][4];
#pragma unroll
    for (int i = 0; i < 8; i++)
#pragma unroll
        for (int j = 0; j < 4; j++) acc[i][j] = 0.f;

    for (int k0 = 0; k0 < EMB; k0 += 32) {
#pragma unroll
        for (int q = 0; q < 2; q++) {
            int f = tid + q * 256;
            int r = f >> 3, c4 = f & 7;
            float4 v = *(const float4*)(emb + (size_t)xs[r] * EMB + k0 + c4 * 4);
            *(float4*)(&As[r][c4 * 4]) = v;
        }
#pragma unroll
        for (int q = 0; q < 4; q++) {
            int f = tid + q * 256;
            int r = f >> 5, c4 = f & 31;
            float4 v = *(const float4*)(Wh + (size_t)(k0 + r) * LAT + n0 + c4 * 4);
            *(float4*)(&Bs[r][c4 * 4]) = v;
        }
        __syncthreads();

#pragma unroll
        for (int kq = 0; kq < 8; kq++) {
            float bt[4][4];
#pragma unroll
            for (int kk = 0; kk < 4; kk++) {
                float4 t = *(float4*)(&Bs[kq * 4 + kk][tx * 4]);
                bt[kk][0] = t.x; bt[kk][1] = t.y; bt[kk][2] = t.z; bt[kk][3] = t.w;
            }
#pragma unroll
            for (int i = 0; i < 8; i++) {
                float4 a4 = *(float4*)(&As[ty * 8 + i][kq * 4]);
#pragma unroll
                for (int j = 0; j < 4; j++) {
                    acc[i][j] = fmaf(a4.x, bt[0][j],
                                fmaf(a4.y, bt[1][j],
                                fmaf(a4.z, bt[2][j],
                                fmaf(a4.w, bt[3][j], acc[i][j]))));
                }
            }
        }
        __syncthreads();
    }

    float4 bh4 = *(const float4*)(bh + n0 + tx * 4);
#pragma unroll
    for (int i = 0; i < 8; i++) {
        float4 o;
        o.x = acc[i][0] + bh4.x;
        o.y = acc[i][1] + bh4.y;
        o.z = acc[i][2] + bh4.z;
        o.w = acc[i][3] + bh4.w;
        *(float4*)(g_xproj + (size_t)(m0 + ty * 8 + i) * LAT + n0 + tx * 4) = o;
    }
}

// ============================================================================
// Kernel 1b: build g_WoB — B fragment-major fp16 for m16n8k16.
// Panel (nt, kt32) = 8192 halfs (16 KB): 32 blocks [wn(4)][kk(2)][np(4)],
// block = 32 lanes x 4 regs x 2 halfs.
//   reg0: (k0,   n0)(k0+1, n0)   reg1: (k0+8, n0)(k0+9, n0)
//   reg2: (k0,   n0+8)(k0+1,n0+8) reg3: (k0+8, n0+8)(k0+9,n0+8)
//   n0 = wn*64 + np*16 + lane>>2 ;  k0 = kk*16 + (lane&3)*2
// Grid (125, 16), 256 threads: each warp does 4 blocks.
// ============================================================================
__global__ void __launch_bounds__(256) k_prepB(const float* __restrict__ Wo)
{
    const int nt = blockIdx.x, kt = blockIdx.y;
    const int w = threadIdx.x >> 5, lane = threadIdx.x & 31;
    __half* panel = g_WoB + ((size_t)nt * 16 + kt) * 8192;

#pragma unroll
    for (int bi = 0; bi < 4; bi++) {
        int b  = w * 4 + bi;                 // 0..31
        int wn = b >> 3, kk = (b >> 2) & 1, np = b & 3;
        int n0 = nt * 256 + wn * 64 + np * 16 + (lane >> 2);
        int k0 = kt * 32 + kk * 16 + (lane & 3) * 2;
        const float* base = Wo + (size_t)k0 * OUT_DIM + n0;
        uint4 v;
        v.x = pack_h2(base[0],                       base[(size_t)1 * OUT_DIM]);
        v.y = pack_h2(base[(size_t)8 * OUT_DIM],     base[(size_t)9 * OUT_DIM]);
        v.z = pack_h2(base[8],                       base[(size_t)1 * OUT_DIM + 8]);
        v.w = pack_h2(base[(size_t)8 * OUT_DIM + 8], base[(size_t)9 * OUT_DIM + 8]);
        *(uint4*)(panel + (size_t)b * 256 + lane * 8) = v;
    }
}

// ============================================================================
// Kernel 2: persistent recurrence (round-4 L2-barrier version, fp16 g_hA).
// ============================================================================
__global__ void __launch_bounds__(256, 1) k_rnn(const float* __restrict__ Wh,
                                                float* __restrict__ hid)
{
    __shared__ ulonglong2 hsT[512];
    __shared__ float      red[8][4][32];

    const int tid  = threadIdx.x;
    const int s    = tid >> 5;
    const int c    = tid & 31;
    const int bgrp = blockIdx.x >> 4;
    const int cgrp = blockIdx.x & 15;
    const int b0   = bgrp * 4;
    const int col  = cgrp * 32 + c;

    float w[64];
#pragma unroll
    for (int i = 0; i < 64; i++)
        w[i] = Wh[(size_t)(EMB + s * 64 + i) * LAT + col];

    unsigned target = 0;
    for (int t = 0; t < T_STEPS; t++) {
#pragma unroll
        for (int hq = 0; hq < 2; hq++) {
            int k = tid + hq * 256;
            float v0, v1, v2, v3;
            if (t == 0) {
                v0 = v1 = v2 = v3 = 0.f;
            } else {
                const float* hp = hid + (size_t)((t - 1) * BATCH + b0) * LAT + k;
                v0 = __ldcg(hp);
                v1 = __ldcg(hp + LAT);
                v2 = __ldcg(hp + 2 * LAT);
                v3 = __ldcg(hp + 3 * LAT);
            }
            hsT[k] = make_ulonglong2(pack2(v0, v1), pack2(v2, v3));
        }
        __syncthreads();

        unsigned long long acc01 = 0ull, acc23 = 0ull;
        const ulonglong2* hp = hsT + s * 64;
#pragma unroll
        for (int i = 0; i < 64; i++) {
            ulonglong2 hv = hp[i];
            unsigned long long w2 = pack2(w[i], w[i]);
            ffma2(acc01, hv.x, w2);
            ffma2(acc23, hv.y, w2);
        }
        float a0, a1, a2, a3;
        unpack2(acc01, a0, a1);
        unpack2(acc23, a2, a3);
        red[s][0][c] = a0;
        red[s][1][c] = a1;
        red[s][2][c] = a2;
        red[s][3][c] = a3;
        __syncthreads();

        if (tid < 128) {
            int bb = tid >> 5, cc = tid & 31;
            float v = 0.f;
#pragma unroll
            for (int ss = 0; ss < 8; ss++) v += red[ss][bb][cc];
            int colw = cgrp * 32 + cc;
            int rowi = t * BATCH + b0 + bb;
            size_t row = (size_t)rowi;
            v += g_xproj[row * LAT + colw];
            v = fmaxf(v, 0.f);
            hid[row * LAT + colw] = v;
            g_hA[hA_index_h(rowi, colw)] = __float2half_rn(v);
            __threadfence();
        }
        __syncthreads();

        target += 16;
        if (tid == 0) {
            atomicAdd(&g_cnt[bgrp], 1u);
            while (*((volatile unsigned*)&g_cnt[bgrp]) < target) {
                __nanosleep(32);
            }
            __threadfence();
        }
        __syncthreads();
    }
}

// ============================================================================
// Kernel 3: out = hid @ Wo + bo.  mma.sync fp16 (m16n8k16), fragment-major
// fp16 operands, cp.async.bulk 8-stage mbarrier ring. CTA tile 128m x 256n,
// BK=32. 8 warps (2m x 4n), warp tile 64x64. Grid (64 mt, 125 nt).
// ============================================================================
#define NSTG 8
#define A_PANEL_B 8192u
#define B_PANEL_B 16384u
#define STG_B (A_PANEL_B + B_PANEL_B)            // 24576
#define TILE_OFF 1024u
#define OUT_SMEM (TILE_OFF + NSTG * STG_B)       // 197632 B

__global__ void __launch_bounds__(256, 1) k_out_mma(const float* __restrict__ bo,
                                                    float* __restrict__ out)
{
    extern __shared__ char smem[];
    const uint32_t smem_base = smaddr(smem);
    const uint32_t fullb  = smem_base;           // 8 x 8B
    const uint32_t emptyb = smem_base + 64;      // 8 x 8B

    const int tid  = threadIdx.x;
    const int warp = tid >> 5;
    const int lane = tid & 31;
    const int wm   = warp >> 2;   // 0..1
    const int wn   = warp & 3;    // 0..3
    const int mt   = blockIdx.x;  // 0..63
    const int nt   = blockIdx.y;  // 0..124

    if (tid == 0) {
#pragma unroll
        for (int s2 = 0; s2 < NSTG; s2++) {
            MBARRIER_INIT(fullb  + s2 * 8, 1);
            MBARRIER_INIT(emptyb + s2 * 8, 8);
        }
        FENCE_ASYNC_SHARED();
    }
    __syncthreads();

    const __half* gA = g_hA  + (size_t)mt * 16 * 4096;
    const __half* gB = g_WoB + (size_t)nt * 16 * 8192;

    auto issue = [&](int cc) {
        int st = cc & 7;
        uint32_t sa = smem_base + TILE_OFF + st * STG_B;
        MBARRIER_EXPECT_TX(fullb + st * 8, STG_B);
        bulk_g2s(sa,             gA + (size_t)cc * 4096, A_PANEL_B, fullb + st * 8);
        bulk_g2s(sa + A_PANEL_B, gB + (size_t)cc * 8192, B_PANEL_B, fullb + st * 8);
    };

    if (tid == 0) {
#pragma unroll
        for (int c = 0; c < 8; c++) issue(c);
    }

    float acc[4][8][4];
#pragma unroll
    for (int mi = 0; mi < 4; mi++)
#pragma unroll
        for (int ni = 0; ni < 8; ni++)
#pragma unroll
            for (int j = 0; j < 4; j++) acc[mi][ni][j] = 0.f;

#pragma unroll 1
    for (int c = 0; c < 16; c++) {
        const int st = c & 7;
        const int ph = (c >> 3) & 1;
        MBARRIER_WAIT_PARITY(fullb + st * 8, ph);

        const uint32_t sa = smem_base + TILE_OFF + st * STG_B;
        const uint32_t sb = sa + A_PANEL_B;

#pragma unroll
        for (int kk = 0; kk < 2; kk++) {
            uint32_t af[4][4];
#pragma unroll
            for (int mi = 0; mi < 4; mi++)
                lds128(sa + (uint32_t)((((wm * 4 + mi) * 2 + kk) * 32 + lane) * 16),
                       af[mi][0], af[mi][1], af[mi][2], af[mi][3]);
            uint32_t bf[4][4];
#pragma unroll
            for (int np = 0; np < 4; np++)
                lds128(sb + (uint32_t)(((wn * 8 + kk * 4 + np) * 32 + lane) * 16),
                       bf[np][0], bf[np][1], bf[np][2], bf[np][3]);
#pragma unroll
            for (int mi = 0; mi < 4; mi++) {
#pragma unroll
                for (int np = 0; np < 4; np++) {
                    mma_f16(acc[mi][2 * np][0], acc[mi][2 * np][1],
                            acc[mi][2 * np][2], acc[mi][2 * np][3],
                            af[mi][0], af[mi][1], af[mi][2], af[mi][3],
                            bf[np][0], bf[np][1]);
                    mma_f16(acc[mi][2 * np + 1][0], acc[mi][2 * np + 1][1],
                            acc[mi][2 * np + 1][2], acc[mi][2 * np + 1][3],
                            af[mi][0], af[mi][1], af[mi][2], af[mi][3],
                            bf[np][2], bf[np][3]);
                }
            }
        }

        if (elect_one_pred()) MBARRIER_ARRIVE(emptyb + st * 8);
        if (tid == 0 && c < 8) {
            MBARRIER_WAIT_PARITY(emptyb + st * 8, 0);
            issue(c + 8);
        }
    }

    // ---- epilogue: direct register -> global stores, + bias ----
    const int m0 = mt * 128 + wm * 64;
    const int n0 = nt * 256 + wn * 64;
#pragma unroll
    for (int ni = 0; ni < 8; ni++) {
        int ccol = n0 + ni * 8 + (lane & 3) * 2;
        float2 b2 = *(const float2*)(bo + ccol);
#pragma unroll
        for (int mi = 0; mi < 4; mi++) {
            int r = m0 + mi * 16 + (lane >> 2);
            float2 o0, o1;
            o0.x = acc[mi][ni][0] + b2.x;
            o0.y = acc[mi][ni][1] + b2.y;
            o1.x = acc[mi][ni][2] + b2.x;
            o1.y = acc[mi][ni][3] + b2.y;
            *(float2*)(out + (size_t)r * OUT_DIM + ccol)       = o0;
            *(float2*)(out + (size_t)(r + 8) * OUT_DIM + ccol) = o1;
        }
    }
}

// ============================================================================
extern "C" void kernel_launch(void* const* d_in, const int* in_sizes, int n_in,
                              void* d_out, int out_size)
{
    (void)in_sizes; (void)n_in; (void)out_size;
    const int*   x   = (const int*)d_in[0];
    const float* emb = (const float*)d_in[1];
    const float* Wh  = (const float*)d_in[2];
    const float* bh  = (const float*)d_in[3];
    const float* Wo  = (const float*)d_in[4];
    const float* bo  = (const float*)d_in[5];

    float* out = (float*)d_out;                       // [8192, 32000]
    float* hid = out + (size_t)MROWS * OUT_DIM;       // [8192, 512]

    cudaFuncSetAttribute(k_out_mma, cudaFuncAttributeMaxDynamicSharedMemorySize,
                         OUT_SMEM);

    k_xproj<<<dim3(4, 128), 256>>>(x, emb, Wh, bh);
    k_prepB<<<dim3(OUT_DIM / 256, LAT / 32), 256>>>(Wo);
    k_rnn<<<128, 256>>>(Wh, hid);
    k_out_mma<<<dim3(MROWS / 128, OUT_DIM / 256), 256, OUT_SMEM>>>(bo, out);
}

// round 7
// speedup vs baseline: 1.7228x; 1.1740x over previous
#include <cuda_runtime.h>
#include <cuda_fp16.h>
#include <cstdint>
#include <cstddef>

#define T_STEPS 256
#define BATCH   32
#define EMB     256
#define LAT     512
#define OUT_DIM 32000
#define MROWS   (T_STEPS * BATCH)   // 8192

// ---------------- device scratch (no allocations allowed) ------------------
__device__ float    g_xproj[(size_t)MROWS * LAT];      // 16 MB
__device__ __half   g_hA[(size_t)MROWS * LAT];         // 8 MB, A fragment-major fp16
__device__ __half   g_WoB[(size_t)OUT_DIM * LAT];      // 32.75 MB, B fragment-major fp16
__device__ unsigned g_cnt[8];                           // rnn barrier counters

// ---------------- helpers ----------------------------------------------------
__device__ __forceinline__ unsigned long long pack2(float a, float b) {
    unsigned long long r;
    asm("mov.b64 %0, {%1, %2};" : "=l"(r) : "f"(a), "f"(b));
    return r;
}
__device__ __forceinline__ void unpack2(unsigned long long v, float& a, float& b) {
    asm("mov.b64 {%0, %1}, %2;" : "=f"(a), "=f"(b) : "l"(v));
}
__device__ __forceinline__ void ffma2(unsigned long long& acc, unsigned long long h,
                                      unsigned long long w) {
    asm("fma.rn.f32x2 %0, %1, %2, %0;" : "+l"(acc) : "l"(h), "l"(w));
}
__device__ __forceinline__ uint32_t pack_h2(float lo, float hi) {
    __half2 h = __floats2half2_rn(lo, hi);
    return *(uint32_t*)&h;
}
__device__ __forceinline__ uint32_t smaddr(const void* p) {
    return (uint32_t)__cvta_generic_to_shared(p);
}
__device__ __forceinline__ uint32_t elect_one_pred() {
    uint32_t pred;
    asm volatile(
        "{\n\t.reg .pred p;\n\t"
        "elect.sync _|p, 0xFFFFFFFF;\n\t"
        "selp.b32 %0, 1, 0, p;\n\t}"
        : "=r"(pred));
    return pred;
}
__device__ __forceinline__ void lds128(uint32_t a, uint32_t& r0, uint32_t& r1,
                                       uint32_t& r2, uint32_t& r3) {
    asm volatile("ld.shared.v4.b32 {%0, %1, %2, %3}, [%4];"
                 : "=r"(r0), "=r"(r1), "=r"(r2), "=r"(r3) : "r"(a));
}
__device__ __forceinline__ void bulk_g2s(uint32_t dst, const void* src,
                                         uint32_t bytes, uint32_t mbar) {
    asm volatile(
        "cp.async.bulk.shared::cluster.global.mbarrier::complete_tx::bytes "
        "[%0], [%1], %2, [%3];"
        :: "r"(dst), "l"(src), "r"(bytes), "r"(mbar) : "memory");
}
__device__ __forceinline__ void red_release_add(unsigned* p, unsigned v) {
    asm volatile("red.release.gpu.global.add.u32 [%0], %1;"
                 :: "l"(p), "r"(v) : "memory");
}
__device__ __forceinline__ unsigned ld_acquire(const unsigned* p) {
    unsigned v;
    asm volatile("ld.global.acquire.gpu.u32 %0, [%1];" : "=r"(v) : "l"(p) : "memory");
    return v;
}
#define MBARRIER_INIT(mbar, cnt) \
    asm volatile("mbarrier.init.shared.b64 [%0], %1;" \
                 :: "r"((uint32_t)(mbar)), "r"((uint32_t)(cnt)) : "memory")
#define MBARRIER_ARRIVE(mbar) \
    asm volatile("mbarrier.arrive.shared.b64 _, [%0];" \
                 :: "r"((uint32_t)(mbar)) : "memory")
#define MBARRIER_EXPECT_TX(mbar, tx) \
    asm volatile("mbarrier.arrive.expect_tx.shared.b64 _, [%0], %1;" \
                 :: "r"((uint32_t)(mbar)), "r"((uint32_t)(tx)) : "memory")
#define MBARRIER_WAIT_PARITY(mbar, par) do {                                   \
    uint32_t _m = (uint32_t)(mbar);                                            \
    uint32_t _p = (uint32_t)(par);                                             \
    asm volatile(                                                              \
        "{\n\t.reg .pred P1;\n\t"                                              \
        "WL_%=:\n\t"                                                           \
        "mbarrier.try_wait.parity.acquire.cta.shared::cta.b64 P1, [%0], %1, 0x989680;\n\t" \
        "@P1 bra.uni WD_%=;\n\t"                                               \
        "bra.uni WL_%=;\n\t"                                                   \
        "WD_%=:\n\t}"                                                          \
        :: "r"(_m), "r"(_p) : "memory");                                       \
} while (0)
#define FENCE_ASYNC_SHARED() asm volatile("fence.proxy.async.shared::cta;" ::: "memory")

__device__ __forceinline__ void mma_f16(float& c0, float& c1, float& c2, float& c3,
                                        uint32_t a0, uint32_t a1, uint32_t a2, uint32_t a3,
                                        uint32_t b0, uint32_t b1) {
    asm volatile(
        "mma.sync.aligned.m16n8k16.row.col.f32.f16.f16.f32 "
        "{%0,%1,%2,%3}, {%4,%5,%6,%7}, {%8,%9}, {%0,%1,%2,%3};"
        : "+f"(c0), "+f"(c1), "+f"(c2), "+f"(c3)
        : "r"(a0), "r"(a1), "r"(a2), "r"(a3), "r"(b0), "r"(b1));
}

// Fragment-major index (in halfs) for A value at (row m, col k), fp16 m16n8k16.
__device__ __forceinline__ size_t hA_index_h(int m, int k) {
    int mt = m >> 7, mi16 = (m >> 4) & 7, r = m & 15;
    int kt = k >> 5, kk = (k >> 4) & 1, kb = k & 15;
    int lane = (r & 7) * 4 + ((kb >> 1) & 3);
    int j = (r >> 3) + 2 * (kb >> 3);
    int h = kb & 1;
    return ((size_t)mt * 16 + kt) * 4096
         + (size_t)((((mi16 * 2 + kk) * 32 + lane) * 4 + j) * 2 + h);
}

// ============================================================================
// Kernel 1: xproj = gather(emb, x) @ W_h[:256] + b_h  (fp32 SIMT)
// ============================================================================
__global__ void __launch_bounds__(256) k_xproj(const int* __restrict__ x,
                                               const float* __restrict__ emb,
                                               const float* __restrict__ Wh,
                                               const float* __restrict__ bh)
{
    __shared__ float As[64][36];
    __shared__ float Bs[32][132];
    __shared__ int   xs[64];

    const int tid = threadIdx.x;
    const int m0  = blockIdx.y * 64;
    const int n0  = blockIdx.x * 128;

    if (blockIdx.x == 0 && blockIdx.y == 0 && tid < 8) g_cnt[tid] = 0;

    if (tid < 64) xs[tid] = x[m0 + tid];
    __syncthreads();

    const int ty = tid >> 5;
    const int tx = tid & 31;

    float acc[8][4];
#pragma unroll
    for (int i = 0; i < 8; i++)
#pragma unroll
        for (int j = 0; j < 4; j++) acc[i][j] = 0.f;

    for (int k0 = 0; k0 < EMB; k0 += 32) {
#pragma unroll
        for (int q = 0; q < 2; q++) {
            int f = tid + q * 256;
            int r = f >> 3, c4 = f & 7;
            float4 v = *(const float4*)(emb + (size_t)xs[r] * EMB + k0 + c4 * 4);
            *(float4*)(&As[r][c4 * 4]) = v;
        }
#pragma unroll
        for (int q = 0; q < 4; q++) {
            int f = tid + q * 256;
            int r = f >> 5, c4 = f & 31;
            float4 v = *(const float4*)(Wh + (size_t)(k0 + r) * LAT + n0 + c4 * 4);
            *(float4*)(&Bs[r][c4 * 4]) = v;
        }
        __syncthreads();

#pragma unroll
        for (int kq = 0; kq < 8; kq++) {
            float bt[4][4];
#pragma unroll
            for (int kk = 0; kk < 4; kk++) {
                float4 t = *(float4*)(&Bs[kq * 4 + kk][tx * 4]);
                bt[kk][0] = t.x; bt[kk][1] = t.y; bt[kk][2] = t.z; bt[kk][3] = t.w;
            }
#pragma unroll
            for (int i = 0; i < 8; i++) {
                float4 a4 = *(float4*)(&As[ty * 8 + i][kq * 4]);
#pragma unroll
                for (int j = 0; j < 4; j++) {
                    acc[i][j] = fmaf(a4.x, bt[0][j],
                                fmaf(a4.y, bt[1][j],
                                fmaf(a4.z, bt[2][j],
                                fmaf(a4.w, bt[3][j], acc[i][j]))));
                }
            }
        }
        __syncthreads();
    }

    float4 bh4 = *(const float4*)(bh + n0 + tx * 4);
#pragma unroll
    for (int i = 0; i < 8; i++) {
        float4 o;
        o.x = acc[i][0] + bh4.x;
        o.y = acc[i][1] + bh4.y;
        o.z = acc[i][2] + bh4.z;
        o.w = acc[i][3] + bh4.w;
        *(float4*)(g_xproj + (size_t)(m0 + ty * 8 + i) * LAT + n0 + tx * 4) = o;
    }
}

// ============================================================================
// Kernel 1b: build g_WoB — B fragment-major fp16 for m16n8k16.
// ============================================================================
__global__ void __launch_bounds__(256) k_prepB(const float* __restrict__ Wo)
{
    const int nt = blockIdx.x, kt = blockIdx.y;
    const int w = threadIdx.x >> 5, lane = threadIdx.x & 31;
    __half* panel = g_WoB + ((size_t)nt * 16 + kt) * 8192;

#pragma unroll
    for (int bi = 0; bi < 4; bi++) {
        int b  = w * 4 + bi;                 // 0..31
        int wn = b >> 3, kk = (b >> 2) & 1, np = b & 3;
        int n0 = nt * 256 + wn * 64 + np * 16 + (lane >> 2);
        int k0 = kt * 32 + kk * 16 + (lane & 3) * 2;
        const float* base = Wo + (size_t)k0 * OUT_DIM + n0;
        uint4 v;
        v.x = pack_h2(base[0],                       base[(size_t)1 * OUT_DIM]);
        v.y = pack_h2(base[(size_t)8 * OUT_DIM],     base[(size_t)9 * OUT_DIM]);
        v.z = pack_h2(base[8],                       base[(size_t)1 * OUT_DIM + 8]);
        v.w = pack_h2(base[(size_t)8 * OUT_DIM + 8], base[(size_t)9 * OUT_DIM + 8]);
        *(uint4*)(panel + (size_t)b * 256 + lane * 8) = v;
    }
}

// ============================================================================
// Kernel 2: persistent recurrence. L2 exchange; release-REDG + acquire-spin
// barrier (no threadfence, no nanosleep); xproj prefetched at step top.
// ============================================================================
__global__ void __launch_bounds__(256, 1) k_rnn(const float* __restrict__ Wh,
                                                float* __restrict__ hid)
{
    __shared__ ulonglong2 hsT[512];
    __shared__ float      red[8][4][32];

    const int tid  = threadIdx.x;
    const int s    = tid >> 5;
    const int c    = tid & 31;
    const int bgrp = blockIdx.x >> 4;
    const int cgrp = blockIdx.x & 15;
    const int b0   = bgrp * 4;
    const int col  = cgrp * 32 + c;

    float w[64];
#pragma unroll
    for (int i = 0; i < 64; i++)
        w[i] = Wh[(size_t)(EMB + s * 64 + i) * LAT + col];

    unsigned target = 0;
    for (int t = 0; t < T_STEPS; t++) {
        // ---- prefetch xproj for this step (off the critical reduce path) ----
        float xp = 0.f;
        if (tid < 128) {
            xp = __ldg(g_xproj + (size_t)(t * BATCH + b0 + (tid >> 5)) * LAT
                       + cgrp * 32 + (tid & 31));
        }

        // ---- stage h_{t-1} transposed into smem ----
#pragma unroll
        for (int hq = 0; hq < 2; hq++) {
            int k = tid + hq * 256;
            float v0, v1, v2, v3;
            if (t == 0) {
                v0 = v1 = v2 = v3 = 0.f;
            } else {
                const float* hp = hid + (size_t)((t - 1) * BATCH + b0) * LAT + k;
                v0 = __ldcg(hp);
                v1 = __ldcg(hp + LAT);
                v2 = __ldcg(hp + 2 * LAT);
                v3 = __ldcg(hp + 3 * LAT);
            }
            hsT[k] = make_ulonglong2(pack2(v0, v1), pack2(v2, v3));
        }
        __syncthreads();

        // ---- partial matvec: 64 k-values, 4 batches, 1 col ----
        unsigned long long acc01 = 0ull, acc23 = 0ull;
        const ulonglong2* hp = hsT + s * 64;
#pragma unroll
        for (int i = 0; i < 64; i++) {
            ulonglong2 hv = hp[i];
            unsigned long long w2 = pack2(w[i], w[i]);
            ffma2(acc01, hv.x, w2);
            ffma2(acc23, hv.y, w2);
        }
        float a0, a1, a2, a3;
        unpack2(acc01, a0, a1);
        unpack2(acc23, a2, a3);
        red[s][0][c] = a0;
        red[s][1][c] = a1;
        red[s][2][c] = a2;
        red[s][3][c] = a3;
        __syncthreads();

        // ---- reduce 8 slices, add xproj, relu, write h_t ----
        if (tid < 128) {
            int bb = tid >> 5, cc = tid & 31;
            float v = xp;
#pragma unroll
            for (int ss = 0; ss < 8; ss++) v += red[ss][bb][cc];
            int colw = cgrp * 32 + cc;
            int rowi = t * BATCH + b0 + bb;
            v = fmaxf(v, 0.f);
            hid[(size_t)rowi * LAT + colw] = v;
            g_hA[hA_index_h(rowi, colw)] = __float2half_rn(v);
        }
        __syncthreads();   // all h stores issued (CTA-wide happens-before)

        // ---- group barrier: release-REDG arrive, acquire-load spin ----
        target += 16;
        if (tid == 0) {
            red_release_add(&g_cnt[bgrp], 1u);
            while (ld_acquire(&g_cnt[bgrp]) < target) { }
        }
        __syncthreads();
    }
}

// ============================================================================
// Kernel 3: out = hid @ Wo + bo.  mma.sync fp16 (m16n8k16), fragment-major
// fp16 operands, cp.async.bulk 8-stage mbarrier ring. (unchanged, round 6)
// ============================================================================
#define NSTG 8
#define A_PANEL_B 8192u
#define B_PANEL_B 16384u
#define STG_B (A_PANEL_B + B_PANEL_B)            // 24576
#define TILE_OFF 1024u
#define OUT_SMEM (TILE_OFF + NSTG * STG_B)       // 197632 B

__global__ void __launch_bounds__(256, 1) k_out_mma(const float* __restrict__ bo,
                                                    float* __restrict__ out)
{
    extern __shared__ char smem[];
    const uint32_t smem_base = smaddr(smem);
    const uint32_t fullb  = smem_base;
    const uint32_t emptyb = smem_base + 64;

    const int tid  = threadIdx.x;
    const int warp = tid >> 5;
    const int lane = tid & 31;
    const int wm   = warp >> 2;
    const int wn   = warp & 3;
    const int mt   = blockIdx.x;
    const int nt   = blockIdx.y;

    if (tid == 0) {
#pragma unroll
        for (int s2 = 0; s2 < NSTG; s2++) {
            MBARRIER_INIT(fullb  + s2 * 8, 1);
            MBARRIER_INIT(emptyb + s2 * 8, 8);
        }
        FENCE_ASYNC_SHARED();
    }
    __syncthreads();

    const __half* gA = g_hA  + (size_t)mt * 16 * 4096;
    const __half* gB = g_WoB + (size_t)nt * 16 * 8192;

    auto issue = [&](int cc) {
        int st = cc & 7;
        uint32_t sa = smem_base + TILE_OFF + st * STG_B;
        MBARRIER_EXPECT_TX(fullb + st * 8, STG_B);
        bulk_g2s(sa,             gA + (size_t)cc * 4096, A_PANEL_B, fullb + st * 8);
        bulk_g2s(sa + A_PANEL_B, gB + (size_t)cc * 8192, B_PANEL_B, fullb + st * 8);
    };

    if (tid == 0) {
#pragma unroll
        for (int c = 0; c < 8; c++) issue(c);
    }

    float acc[4][8][4];
#pragma unroll
    for (int mi = 0; mi < 4; mi++)
#pragma unroll
        for (int ni = 0; ni < 8; ni++)
#pragma unroll
            for (int j = 0; j < 4; j++) acc[mi][ni][j] = 0.f;

#pragma unroll 1
    for (int c = 0; c < 16; c++) {
        const int st = c & 7;
        const int ph = (c >> 3) & 1;
        MBARRIER_WAIT_PARITY(fullb + st * 8, ph);

        const uint32_t sa = smem_base + TILE_OFF + st * STG_B;
        const uint32_t sb = sa + A_PANEL_B;

#pragma unroll
        for (int kk = 0; kk < 2; kk++) {
            uint32_t af[4][4];
#pragma unroll
            for (int mi = 0; mi < 4; mi++)
                lds128(sa + (uint32_t)((((wm * 4 + mi) * 2 + kk) * 32 + lane) * 16),
                       af[mi][0], af[mi][1], af[mi][2], af[mi][3]);
            uint32_t bf[4][4];
#pragma unroll
            for (int np = 0; np < 4; np++)
                lds128(sb + (uint32_t)(((wn * 8 + kk * 4 + np) * 32 + lane) * 16),
                       bf[np][0], bf[np][1], bf[np][2], bf[np][3]);
#pragma unroll
            for (int mi = 0; mi < 4; mi++) {
#pragma unroll
                for (int np = 0; np < 4; np++) {
                    mma_f16(acc[mi][2 * np][0], acc[mi][2 * np][1],
                            acc[mi][2 * np][2], acc[mi][2 * np][3],
                            af[mi][0], af[mi][1], af[mi][2], af[mi][3],
                            bf[np][0], bf[np][1]);
                    mma_f16(acc[mi][2 * np + 1][0], acc[mi][2 * np + 1][1],
                            acc[mi][2 * np + 1][2], acc[mi][2 * np + 1][3],
                            af[mi][0], af[mi][1], af[mi][2], af[mi][3],
                            bf[np][2], bf[np][3]);
                }
            }
        }

        if (elect_one_pred()) MBARRIER_ARRIVE(emptyb + st * 8);
        if (tid == 0 && c < 8) {
            MBARRIER_WAIT_PARITY(emptyb + st * 8, 0);
            issue(c + 8);
        }
    }

    // ---- epilogue: direct register -> global stores, + bias ----
    const int m0 = mt * 128 + wm * 64;
    const int n0 = nt * 256 + wn * 64;
#pragma unroll
    for (int ni = 0; ni < 8; ni++) {
        int ccol = n0 + ni * 8 + (lane & 3) * 2;
        float2 b2 = *(const float2*)(bo + ccol);
#pragma unroll
        for (int mi = 0; mi < 4; mi++) {
            int r = m0 + mi * 16 + (lane >> 2);
            float2 o0, o1;
            o0.x = acc[mi][ni][0] + b2.x;
            o0.y = acc[mi][ni][1] + b2.y;
            o1.x = acc[mi][ni][2] + b2.x;
            o1.y = acc[mi][ni][3] + b2.y;
            *(float2*)(out + (size_t)r * OUT_DIM + ccol)       = o0;
            *(float2*)(out + (size_t)(r + 8) * OUT_DIM + ccol) = o1;
        }
    }
}

// ============================================================================
extern "C" void kernel_launch(void* const* d_in, const int* in_sizes, int n_in,
                              void* d_out, int out_size)
{
    (void)in_sizes; (void)n_in; (void)out_size;
    const int*   x   = (const int*)d_in[0];
    const float* emb = (const float*)d_in[1];
    const float* Wh  = (const float*)d_in[2];
    const float* bh  = (const float*)d_in[3];
    const float* Wo  = (const float*)d_in[4];
    const float* bo  = (const float*)d_in[5];

    float* out = (float*)d_out;                       // [8192, 32000]
    float* hid = out + (size_t)MROWS * OUT_DIM;       // [8192, 512]

    cudaFuncSetAttribute(k_out_mma, cudaFuncAttributeMaxDynamicSharedMemorySize,
                         OUT_SMEM);

    k_xproj<<<dim3(4, 128), 256>>>(x, emb, Wh, bh);
    k_prepB<<<dim3(OUT_DIM / 256, LAT / 32), 256>>>(Wo);
    k_rnn<<<128, 256>>>(Wh, hid);
    k_out_mma<<<dim3(MROWS / 128, OUT_DIM / 256), 256, OUT_SMEM>>>(bo, out);
}